// round 17
// baseline (speedup 1.0000x reference)
#include <cuda_runtime.h>
#include <math.h>
#include <stdint.h>

#define NTOT 32768
#define HTOT 32
#define D    64
#define NT   64
#define NTHREADS 256
#define HALF_BYTES (32 * D * 4)   // 8192 per half-tile

// ---------- tf32 helpers ----------
__device__ __forceinline__ uint32_t f2tf32(float f) {
    uint32_t u;
    asm("cvt.rna.tf32.f32 %0, %1;" : "=r"(u) : "f"(f));
    return u;
}

__device__ __forceinline__ void mma_tf32(float& c0, float& c1, float& c2, float& c3,
                                         uint32_t a0, uint32_t a1, uint32_t a2, uint32_t a3,
                                         uint32_t b0, uint32_t b1) {
    asm volatile(
        "mma.sync.aligned.m16n8k8.row.col.f32.tf32.tf32.f32 "
        "{%0,%1,%2,%3}, {%4,%5,%6,%7}, {%8,%9}, {%0,%1,%2,%3};"
        : "+f"(c0), "+f"(c1), "+f"(c2), "+f"(c3)
        : "r"(a0), "r"(a1), "r"(a2), "r"(a3), "r"(b0), "r"(b1));
}

__device__ __forceinline__ float poly_tanh(float x) {
    float t = x * x;
    float p = fmaf(t, -0.05396825397f, 0.13333333333f);
    p = fmaf(t, p, -0.33333333333f);
    return fmaf(x * t, p, x);
}

__device__ __forceinline__ float logscale_from_ssq(float ssq, float c) {
    float t = c * ssq;
    float p = fmaf(t, 0.22222222f, 0.28571429f);
    p = fmaf(t, p, 0.4f);
    p = fmaf(t, p, 0.66666667f);
    return fmaf(t, p, 2.0f);
}

// Fragment-native swizzled tile layout (conflict-free; rounds 3-15).
__device__ __forceinline__ int chunk_off(int token, int ci, int j) {
    int pb = (token >> 1) & 1;
    int b2 = (token >> 2) & 1;
    int jl = j & 1;
    int j1 = (j >> 1) & 1;
    int slot = ((token & 1) << 2) | (ci ^ (jl ^ pb) ^ ((j1 ^ b2) << 1));
    return ((token >> 1) << 7) | (j << 5) | (slot << 2);
}

// ---------- TMA bulk copy + mbarrier (proven rounds 7-15) ----------
__device__ __forceinline__ void mbar_init(uint32_t mbar, uint32_t cnt) {
    asm volatile("mbarrier.init.shared.b64 [%0], %1;" :: "r"(mbar), "r"(cnt) : "memory");
}
__device__ __forceinline__ void mbar_expect_tx(uint32_t mbar, uint32_t bytes) {
    asm volatile("mbarrier.arrive.expect_tx.shared.b64 _, [%0], %1;"
                 :: "r"(mbar), "r"(bytes) : "memory");
}
__device__ __forceinline__ void bulk_ld(uint32_t sdst, const void* gsrc, uint32_t bytes,
                                        uint32_t mbar) {
    asm volatile(
        "cp.async.bulk.shared::cta.global.mbarrier::complete_tx::bytes [%0], [%1], %2, [%3];"
        :: "r"(sdst), "l"(gsrc), "r"(bytes), "r"(mbar) : "memory");
}
__device__ __forceinline__ void mbar_wait(uint32_t mbar, uint32_t parity) {
    uint32_t done;
    asm volatile(
        "{\n\t.reg .pred p;\n\t"
        "mbarrier.try_wait.parity.acquire.cta.shared::cta.b64 p, [%1], %2;\n\t"
        "selp.b32 %0, 1, 0, p;\n\t}"
        : "=r"(done) : "r"(mbar), "r"(parity) : "memory");
    if (!done) {
        asm volatile(
            "{\n\t.reg .pred P1;\n\t"
            "WAIT_LOOP_%=:\n\t"
            "mbarrier.try_wait.parity.acquire.cta.shared::cta.b64 P1, [%0], %1, 0x989680;\n\t"
            "@P1 bra.uni WAIT_DONE_%=;\n\t"
            "bra.uni WAIT_LOOP_%=;\n\t"
            "WAIT_DONE_%=:\n\t}"
            :: "r"(mbar), "r"(parity) : "memory");
    }
}

#define BAR_HALF(half) asm volatile("bar.sync %0, 128;" :: "r"(1 + (half)) : "memory")

// half-transform: 128 threads transform 32 token rows (tokens half*32 ..).
// thread lt handles rows (lt>>4) + 8*jj (jj=0..3); norms via 16-lane shfl.
__device__ __forceinline__ void transform_half(const float* __restrict__ stagHalf,
                                               uint32_t* __restrict__ tileU,
                                               int lt, int half, float c) {
    const float4* s4 = reinterpret_cast<const float4*>(stagHalf);
    const int col4 = lt & 15;
    const int rb   = lt >> 4;         // 0..7
    const int j    = col4 >> 2;
    const int posR = col4 & 3;
    const int posP = posR ^ ((j & 1) << 1);
    const int tok0 = half * 32 + rb;
    int base[4];
    #pragma unroll
    for (int ci = 0; ci < 4; ci++)
        base[ci] = chunk_off(tok0, ci, j) + posP;

    float4 v[4];
    float  ss[4];
    #pragma unroll
    for (int jj = 0; jj < 4; jj++) v[jj] = s4[lt + 128 * jj];
    #pragma unroll
    for (int jj = 0; jj < 4; jj++) {
        float s = fmaf(v[jj].x, v[jj].x, fmaf(v[jj].y, v[jj].y,
                  fmaf(v[jj].z, v[jj].z, v[jj].w * v[jj].w)));
        #pragma unroll
        for (int off = 1; off < 16; off <<= 1)
            s += __shfl_xor_sync(0xffffffffu, s, off);
        ss[jj] = s;
    }
    #pragma unroll
    for (int jj = 0; jj < 4; jj++) {
        float sc = logscale_from_ssq(ss[jj], c);
        int o = jj << 9;              // +8 rows = +512 floats (pb/b2 invariant)
        tileU[base[0] + o] = f2tf32(v[jj].x * sc);
        tileU[base[1] + o] = f2tf32(v[jj].y * sc);
        tileU[base[2] + o] = f2tf32(v[jj].z * sc);
        tileU[base[3] + o] = f2tf32(v[jj].w * sc);
    }
}

__global__ __launch_bounds__(NTHREADS, 2)
void hyp_attn_kernel(const float* __restrict__ cur,
                     const float* __restrict__ hist,
                     const float* __restrict__ curv,
                     const float* __restrict__ Wq,
                     const float* __restrict__ bq,
                     const float* __restrict__ Wk,
                     const float* __restrict__ bk,
                     const float* __restrict__ av,
                     float* __restrict__ out) {
    extern __shared__ float sm[];
    uint32_t* tile0 = reinterpret_cast<uint32_t*>(sm);        // 4096 u32
    uint32_t* tile1 = reinterpret_cast<uint32_t*>(sm) + 4096; // 4096 u32
    float* stagA = sm + 8192;                                 // 4096 (2 halves)
    float* stagB = sm + 12288;                                // 4096 (2 halves)
    float* lp    = sm + 16384;                                // 256
    uint32_t mbarBase = (uint32_t)__cvta_generic_to_shared(sm + 16640);  // 4 mbars

    const int t    = threadIdx.x;
    const int lane = t & 31;
    const int w    = t >> 5;          // 0..7
    const int half = t >> 7;          // 0/1
    const int lt   = t & 127;
    const int n0   = blockIdx.x * NT;
    const float c  = curv[0];

    // per-half mbar pairs: half*16 + buf*8
    const uint32_t mbarH0 = mbarBase + half * 16;
    const uint32_t mbarH1 = mbarH0 + 8;
    const uint32_t stAu = (uint32_t)__cvta_generic_to_shared(stagA) + half * HALF_BYTES;
    const uint32_t stBu = (uint32_t)__cvta_generic_to_shared(stagB) + half * HALF_BYTES;
    const float* stagAh = stagA + half * 2048;
    const float* stagBh = stagB + half * 2048;

    // warp roles: e-quarter (w&3)*16, token half th = w>>2 (== half)
    const int eq = w & 3;
    const int lr = lane >> 2;
    const int ci = lane & 3;
    const int Tq = half * 32;
    const int r0 = eq * 16 + lr;

    int fb[4];
    #pragma unroll
    for (int j = 0; j < 4; j++) fb[j] = chunk_off(Tq + lr, ci, j);

    // RMW / epilogue ownership: token = t>>2 (half-aligned), d-quarter dq = t&3
    const int tok = t >> 2;
    const int dq  = t & 3;
    int roff[4];
    #pragma unroll
    for (int cc = 0; cc < 4; cc++) roff[cc] = chunk_off(tok, cc, dq);

    const float bias0 = bq[r0]     + bk[r0];
    const float bias1 = bq[r0 + 8] + bk[r0 + 8];
    const float av0   = av[r0];
    const float av1   = av[r0 + 8];

    // ---- mbarrier init + first TMA loads (current tile, per half) ----
    if (lt == 0) {
        mbar_init(mbarH0, 1);
        mbar_init(mbarH1, 1);
        asm volatile("fence.proxy.async.shared::cta;" ::: "memory");
    }
    __syncthreads();                  // all 4 mbars initialized
    if (lt == 0) {
        mbar_expect_tx(mbarH0, HALF_BYTES);
        bulk_ld(stAu, cur + (size_t)(n0 + half * 32) * D, HALF_BYTES, mbarH0);
    }

    // ---- A fragments (Wq first) while the load flies ----
    uint32_t A[8][4];
    #pragma unroll
    for (int kc = 0; kc < 8; kc++) {
        A[kc][0] = f2tf32(Wq[r0 * 64 + kc * 8 + ci]);
        A[kc][1] = f2tf32(Wq[(r0 + 8) * 64 + kc * 8 + ci]);
        A[kc][2] = f2tf32(Wq[r0 * 64 + kc * 8 + ci + 4]);
        A[kc][3] = f2tf32(Wq[(r0 + 8) * 64 + kc * 8 + ci + 4]);
    }

    mbar_wait(mbarH0, 0);             // my half's cur staging visible
    transform_half(stagAh, tile1, lt, half, c);   // cur -> tile1 (own half rows)
    BAR_HALF(half);                   // tile1 half ready; stagA half consumed

    // prefetch history h=0 (stagA) and h=1 (stagB) for this half
    if (lt == 0) {
        mbar_expect_tx(mbarH0, HALF_BYTES);
        bulk_ld(stAu, hist + (size_t)(n0 + half * 32) * D, HALF_BYTES, mbarH0);
        mbar_expect_tx(mbarH1, HALF_BYTES);
        bulk_ld(stBu, hist + ((size_t)NTOT + n0 + half * 32) * D, HALF_BYTES, mbarH1);
    }

    // ---- Q fragments from tile1 (own half rows only) ----
    float qf[4][4];
    #pragma unroll
    for (int nc = 0; nc < 4; nc++) {
        uint4 q[4];
        #pragma unroll
        for (int j = 0; j < 4; j++)
            q[j] = *reinterpret_cast<const uint4*>(&tile1[fb[j] + nc * 512]);
        float c0 = 0.f, c1 = 0.f, c2 = 0.f, c3 = 0.f;
        mma_tf32(c0,c1,c2,c3, A[0][0],A[0][1],A[0][2],A[0][3], q[0].x, q[0].y);
        mma_tf32(c0,c1,c2,c3, A[1][0],A[1][1],A[1][2],A[1][3], q[0].z, q[0].w);
        mma_tf32(c0,c1,c2,c3, A[2][0],A[2][1],A[2][2],A[2][3], q[1].z, q[1].w);
        mma_tf32(c0,c1,c2,c3, A[3][0],A[3][1],A[3][2],A[3][3], q[1].x, q[1].y);
        mma_tf32(c0,c1,c2,c3, A[4][0],A[4][1],A[4][2],A[4][3], q[2].x, q[2].y);
        mma_tf32(c0,c1,c2,c3, A[5][0],A[5][1],A[5][2],A[5][3], q[2].z, q[2].w);
        mma_tf32(c0,c1,c2,c3, A[6][0],A[6][1],A[6][2],A[6][3], q[3].z, q[3].w);
        mma_tf32(c0,c1,c2,c3, A[7][0],A[7][1],A[7][2],A[7][3], q[3].x, q[3].y);
        qf[nc][0] = c0 + bias0;
        qf[nc][1] = c1 + bias0;
        qf[nc][2] = c2 + bias1;
        qf[nc][3] = c3 + bias1;
    }
    // tile1 half not overwritten until h=1's transform (>=2 half-barriers away)

    // ---- swap A fragments to Wk ----
    #pragma unroll
    for (int kc = 0; kc < 8; kc++) {
        A[kc][0] = f2tf32(Wk[r0 * 64 + kc * 8 + ci]);
        A[kc][1] = f2tf32(Wk[(r0 + 8) * 64 + kc * 8 + ci]);
        A[kc][2] = f2tf32(Wk[r0 * 64 + kc * 8 + ci + 4]);
        A[kc][3] = f2tf32(Wk[(r0 + 8) * 64 + kc * 8 + ci + 4]);
    }

    float accR[4][4];
    #pragma unroll
    for (int cc = 0; cc < 4; cc++)
        #pragma unroll
        for (int p = 0; p < 4; p++) accR[cc][p] = 0.f;
    float sreg = 0.f;
    int ph0 = 1, ph1 = 0;

    for (int h = 0; h < HTOT; h++) {
        // per-thread acquire wait on this half's staging buffer
        if (h & 1) { mbar_wait(mbarH1, ph1); ph1 ^= 1; }
        else       { mbar_wait(mbarH0, ph0); ph0 ^= 1; }

        uint32_t* tU = (h & 1) ? tile1 : tile0;
        transform_half((h & 1) ? stagBh : stagAh, tU, lt, half, c);
        BAR_HALF(half);               // B1: tile half ready; staging half consumed

        // TMA load for h+2 into the staging half just freed
        if (h + 2 < HTOT && lt == 0) {
            uint32_t mb   = (h & 1) ? mbarH1 : mbarH0;
            uint32_t sdst = (h & 1) ? stBu : stAu;
            mbar_expect_tx(mb, HALF_BYTES);
            bulk_ld(sdst, hist + ((size_t)(h + 2) * NTOT + n0 + half * 32) * D,
                    HALF_BYTES, mb);
        }

        // K MMA fused with tanh-logit partials (own half's tokens)
        #pragma unroll
        for (int nc = 0; nc < 4; nc++) {
            uint4 q[4];
            #pragma unroll
            for (int j = 0; j < 4; j++)
                q[j] = *reinterpret_cast<const uint4*>(&tU[fb[j] + nc * 512]);
            float c0 = 0.f, c1 = 0.f, c2 = 0.f, c3 = 0.f;
            mma_tf32(c0,c1,c2,c3, A[0][0],A[0][1],A[0][2],A[0][3], q[0].x, q[0].y);
            mma_tf32(c0,c1,c2,c3, A[1][0],A[1][1],A[1][2],A[1][3], q[0].z, q[0].w);
            mma_tf32(c0,c1,c2,c3, A[2][0],A[2][1],A[2][2],A[2][3], q[1].z, q[1].w);
            mma_tf32(c0,c1,c2,c3, A[3][0],A[3][1],A[3][2],A[3][3], q[1].x, q[1].y);
            mma_tf32(c0,c1,c2,c3, A[4][0],A[4][1],A[4][2],A[4][3], q[2].x, q[2].y);
            mma_tf32(c0,c1,c2,c3, A[5][0],A[5][1],A[5][2],A[5][3], q[2].z, q[2].w);
            mma_tf32(c0,c1,c2,c3, A[6][0],A[6][1],A[6][2],A[6][3], q[3].z, q[3].w);
            mma_tf32(c0,c1,c2,c3, A[7][0],A[7][1],A[7][2],A[7][3], q[3].x, q[3].y);
            float t0 = poly_tanh(qf[nc][0] + c0);
            float t1 = poly_tanh(qf[nc][1] + c1);
            float t2 = poly_tanh(qf[nc][2] + c2);
            float t3 = poly_tanh(qf[nc][3] + c3);
            float p0 = fmaf(t0, av0, t2 * av1);
            float p1 = fmaf(t1, av0, t3 * av1);
            #pragma unroll
            for (int off = 4; off < 32; off <<= 1) {
                p0 += __shfl_xor_sync(0xffffffffu, p0, off);
                p1 += __shfl_xor_sync(0xffffffffu, p1, off);
            }
            if (lane < 4) {
                float2 st; st.x = p0; st.y = p1;
                *reinterpret_cast<float2*>(&lp[eq * 64 + Tq + nc * 8 + 2 * lane]) = st;
            }
        }
        BAR_HALF(half);               // B2: this half's logit partials ready

        // softmax accumulation + register RMW (hazards ordered by B1(h+1))
        float L  = lp[tok] + lp[64 + tok] + lp[128 + tok] + lp[192 + tok];
        float pe = __expf(L);         // logits bounded << 88
        sreg += pe;
        #pragma unroll
        for (int cc = 0; cc < 4; cc++) {
            float4 t4 = *reinterpret_cast<const float4*>(&tU[roff[cc]]);
            accR[cc][0] = fmaf(pe, t4.x, accR[cc][0]);
            accR[cc][1] = fmaf(pe, t4.y, accR[cc][1]);
            accR[cc][2] = fmaf(pe, t4.z, accR[cc][2]);
            accR[cc][3] = fmaf(pe, t4.w, accR[cc][3]);
        }
    }

    // ---- epilogue: ws = acc/s ; context = tanh(sc*|ws|/2)/(sc*|ws|) * ws ----
    float sinv = __fdividef(1.f, sreg);
    float ssq = 0.f;
    #pragma unroll
    for (int cc = 0; cc < 4; cc++)
        #pragma unroll
        for (int p = 0; p < 4; p++)
            ssq = fmaf(accR[cc][p], accR[cc][p], ssq);
    ssq += __shfl_xor_sync(0xffffffffu, ssq, 1);
    ssq += __shfl_xor_sync(0xffffffffu, ssq, 2);

    float sc = sqrtf(c);
    float r = sqrtf(ssq) * sinv;
    float u = sc * r;
    float g;
    if (u > 1e-12f) {
        float e = __expf(u);
        g = __fdividef(e - 1.f, (e + 1.f) * u);    // tanh(u/2)/u
    } else {
        g = 0.5f;
    }
    float f = g * sinv;

    const int xo = (dq & 1) << 1;     // posP = posR ^ ((j&1)<<1)
    float4* op = reinterpret_cast<float4*>(out + (size_t)(n0 + tok) * D + dq * 16);
    #pragma unroll
    for (int gi = 0; gi < 4; gi++) {
        int pos = gi ^ xo;
        float4 o;
        o.x = accR[0][pos] * f;
        o.y = accR[1][pos] * f;
        o.z = accR[2][pos] * f;
        o.w = accR[3][pos] * f;
        op[gi] = o;
    }
}

extern "C" void kernel_launch(void* const* d_in, const int* in_sizes, int n_in,
                              void* d_out, int out_size) {
    const float* cur  = (const float*)d_in[0];
    const float* hist = (const float*)d_in[1];
    const float* curv = (const float*)d_in[2];
    const float* Wq   = (const float*)d_in[3];
    const float* bq   = (const float*)d_in[4];
    const float* Wk   = (const float*)d_in[5];
    const float* bk   = (const float*)d_in[6];
    const float* av   = (const float*)d_in[7];
    float* o = (float*)d_out;

    const int smem_bytes = (16640 + 16) * sizeof(float);   // ~67 KB -> 2 CTAs/SM
    cudaFuncSetAttribute(hyp_attn_kernel,
                         cudaFuncAttributeMaxDynamicSharedMemorySize, smem_bytes);
    hyp_attn_kernel<<<NTOT / NT, NTHREADS, smem_bytes>>>(
        cur, hist, curv, Wq, bq, Wk, bk, av, o);
}